// round 15
// baseline (speedup 1.0000x reference)
#include <cuda_runtime.h>
#include <cuda_bf16.h>
#include <math.h>

typedef unsigned long long ull;
typedef unsigned int uint;

#define BATCH  128
#define TSTEPS 256
#define NBLK   128
#define NTHR   512

#define CELL_SLOTS 6291456u            // 384 tiles * 16384 uint4 slots
#define FC_SLOTS   524288u             // 128 tiles * 4096
#define TOT_SLOTS  (CELL_SLOTS + FC_SLOTS)

// dynamic smem map (bytes):
// [0, 98304)        SIX B buffers, 16 KB each (cp.async weight chunks)
// [98304, 132096)   zs[128][66] floats (also final-phase scratch)
// [132096, 140544)  hs[16][132] uints (epilogue wh pair-exchange)
#define ZS_OFF   98304
#define HS_OFF   132096
#define SMEM_BYTES 140544

// ---------------- device scratch -------------------------------------------
__device__ float g_P[2][1024][4096];            // emb @ W_ih(l0)^T, fp32
__device__ float g_c[2][2][BATCH * 1024];
__device__ float g_logitsP[8][BATCH * 1024];    // split-K partials
__device__ int   g_feed[BATCH];
__device__ int   g_ended[BATCH];
__device__ unsigned g_cnt = 0, g_gen = 0;
__device__ uint4 g_WB[TOT_SLOTS];               // pre-fragmented split-bf16 weights
// A in mma-fragment layout: per 64-K chunk = 8192 uints (hi plane 4096 | lo plane 4096)
__device__ uint g_hf[2][2][2][16 * 8192];       // [layer][dir][buf], 16 chunks
__device__ uint g_whf[32 * 8192];               // scrambled fc input, 32 chunks

// ---------------- helpers ----------------------------------------------------
__device__ __forceinline__ uint prmt(uint a, uint b, uint s) {
    uint r; asm("prmt.b32 %0, %1, %2, %3;" : "=r"(r) : "r"(a), "r"(b), "r"(s));
    return r;
}
__device__ __forceinline__ uint b2u(__nv_bfloat162 v) { return *reinterpret_cast<uint*>(&v); }
__device__ __forceinline__ uint pack_split(float v) {
    __nv_bfloat16 h = __float2bfloat16_rn(v);
    float hf = __bfloat162float(h);
    __nv_bfloat16 l = __float2bfloat16_rn(v - hf);
    return (uint)__bfloat16_as_ushort(h) | ((uint)__bfloat16_as_ushort(l) << 16);
}
__device__ __forceinline__ float sigf(float x) { return 1.0f / (1.0f + expf(-x)); }
__device__ __forceinline__ uint s2u(const void* p) {
    uint a;
    asm("{ .reg .u64 t; cvta.to.shared.u64 t, %1; cvt.u32.u64 %0, t; }" : "=r"(a) : "l"(p));
    return a;
}
// fragment slot for value pair (b-row, even j): uint index within an 8192-uint chunk
__device__ __forceinline__ int frag_slot(int brow, int j) {
    int kl = (j >> 4) & 3, pk = (j >> 1) & 7;
    return ((kl * 8 + (brow >> 4)) * 32 + (brow & 7) * 4 + (pk & 3)) * 4
           + ((brow >> 3) & 1) + 2 * (pk >> 2);
}

#define MMA_OP(d, a, bb0, bb1) \
    asm volatile( \
        "mma.sync.aligned.m16n8k16.row.col.f32.bf16.bf16.f32 " \
        "{%0,%1,%2,%3}, {%4,%5,%6,%7}, {%8,%9}, {%0,%1,%2,%3};" \
        : "+f"((d)[0]), "+f"((d)[1]), "+f"((d)[2]), "+f"((d)[3]) \
        : "r"((a)[0]), "r"((a)[1]), "r"((a)[2]), "r"((a)[3]), "r"(bb0), "r"(bb1))

#define CP_ASYNC16(daddr, saddr) \
    asm volatile("cp.async.cg.shared.global [%0], [%1], 16;" :: "r"(daddr), "l"(saddr) : "memory")
#define CP_COMMIT() asm volatile("cp.async.commit_group;" ::: "memory")
#define CP_WAIT4()  asm volatile("cp.async.wait_group 4;" ::: "memory")
#define CP_WAIT3()  asm volatile("cp.async.wait_group 3;" ::: "memory")
#define CP_WAIT2()  asm volatile("cp.async.wait_group 2;" ::: "memory")
#define CP_WAIT1()  asm volatile("cp.async.wait_group 1;" ::: "memory")
#define CP_WAIT0()  asm volatile("cp.async.wait_group 0;" ::: "memory")

// ---------------- f32x2 helpers (pcomp only) --------------------------------
__device__ __forceinline__ ull pk2(float lo, float hi) {
    ull r; asm("mov.b64 %0, {%1,%2};" : "=l"(r) : "f"(lo), "f"(hi)); return r;
}
__device__ __forceinline__ void fma2(ull& d, ull a, ull b) {
    asm("fma.rn.f32x2 %0, %1, %2, %0;" : "+l"(d) : "l"(a), "l"(b));
}
__device__ __forceinline__ float2 unpk(ull v) {
    float2 r; asm("mov.b64 {%0,%1}, %2;" : "=f"(r.x), "=f"(r.y) : "l"(v)); return r;
}

// ---------------- software grid barrier --------------------------------------
__device__ __forceinline__ void gbar() {
    __threadfence();
    __syncthreads();
    if (threadIdx.x == 0) {
        unsigned gen = atomicAdd(&g_gen, 0u);
        unsigned arrived = atomicAdd(&g_cnt, 1u);
        if (arrived == NBLK - 1u) {
            atomicExch(&g_cnt, 0u);
            __threadfence();
            atomicAdd(&g_gen, 1u);
        } else {
            while (atomicAdd(&g_gen, 0u) == gen) { __nanosleep(64); }
        }
        __threadfence();
    }
    __syncthreads();
}

// ---------------- init: h fragments + c + feed --------------------------------
__device__ void init_phase(int bid, const int* __restrict__ yy,
                           const float* __restrict__ h_t,
                           const float* __restrict__ h_tr,
                           const float* __restrict__ c0,
                           const float* __restrict__ c0r) {
    const int gid0 = bid * NTHR + threadIdx.x;
    const int LBH = BATCH * 1024;
    // h -> fragment layout, buffer 0
    for (int i = gid0; i < 2 * 2 * 128 * 512; i += NBLK * NTHR) {
        int l = i >> 17;
        int rem = i & 131071;
        int dr = rem >> 16;
        int rem2 = rem & 65535;
        int b = rem2 >> 9;
        int pj = rem2 & 511;
        int j = pj * 2;
        const float* src = (dr ? h_tr : h_t) + (size_t)l * LBH + b * 1024 + j;
        uint ps0 = pack_split(src[0]);
        uint ps1 = pack_split(src[1]);
        uint hiU = prmt(ps0, ps1, 0x5410), loU = prmt(ps0, ps1, 0x7632);
        int cch = j >> 6;
        int slot = frag_slot(b, j);
        uint* hf = &g_hf[l][dr][0][0];
        hf[cch * 8192 + slot] = hiU;
        hf[cch * 8192 + 4096 + slot] = loU;
    }
    for (int i = gid0; i < 2 * LBH; i += NBLK * NTHR) {
        int l = i / LBH, r = i % LBH, j = r & 1023;
        g_c[l][0][r] = c0[l * 1024 + j];
        g_c[l][1][r] = c0r[l * 1024 + j];
    }
    if (bid == 0 && threadIdx.x < BATCH) {
        g_feed[threadIdx.x] = yy[threadIdx.x * TSTEPS];
        g_ended[threadIdx.x] = 0;
    }
}

// ---------------- setup: split + pre-fragment weights ------------------------
__device__ void setup_weights(int bid,
    const float* __restrict__ W_ih, const float* __restrict__ W_hh,
    const float* __restrict__ W_ihr, const float* __restrict__ W_hhr,
    const float* __restrict__ fcW) {
    for (uint s = bid * NTHR + threadIdx.x; s < TOT_SLOTS; s += NBLK * NTHR) {
        const float* p;
        if (s < CELL_SLOTS) {
            uint tile = s >> 14, rem = s & 16383u;
            uint ks = rem >> 8, nf = (rem >> 5) & 7, lane = rem & 31;
            uint dir = tile / 192, seg = (tile / 64) % 3, jt = tile & 63;
            const float* W;
            if (seg == 0)      W = dir ? W_hhr : W_hh;
            else if (seg == 1) W = (dir ? W_ihr : W_ih) + (size_t)4096 * 1024;
            else               W = (dir ? W_hhr : W_hh) + (size_t)4096 * 1024;
            uint n = nf * 8 + (lane >> 2);
            uint row = (n >> 4) * 1024 + jt * 16 + (n & 15);
            uint kb = ks * 16 + (lane & 3) * 2;
            p = W + (size_t)row * 1024 + kb;
        } else {
            uint srel = s - CELL_SLOTS;
            uint f = srel >> 12, rem = srel & 4095u;
            uint ks = rem >> 8, nf = (rem >> 5) & 7, lane = rem & 31;
            uint et = f >> 3, ks2 = f & 7;
            uint n = nf * 8 + (lane >> 2);
            uint row = et * 64 + n;
            uint kb = ks2 * 256 + ks * 16 + (lane & 3) * 2;
            p = fcW + (size_t)row * 2048 + kb;
        }
        float2 r01 = __ldg((const float2*)p);
        float2 r89 = __ldg((const float2*)(p + 8));
        __nv_bfloat162 H01 = __floats2bfloat162_rn(r01.x, r01.y);
        __nv_bfloat162 H89 = __floats2bfloat162_rn(r89.x, r89.y);
        __nv_bfloat162 L01 = __floats2bfloat162_rn(r01.x - __bfloat162float(H01.x),
                                                   r01.y - __bfloat162float(H01.y));
        __nv_bfloat162 L89 = __floats2bfloat162_rn(r89.x - __bfloat162float(H89.x),
                                                   r89.y - __bfloat162float(H89.y));
        g_WB[s] = make_uint4(b2u(H01), b2u(H89), b2u(L01), b2u(L89));
    }
}

// ---------------- pcomp (fp32 f32x2, 512 thr): P = emb @ W_ih(l0)^T ----------
__device__ void pcomp_phase(char* dsm, int bid, const float* __restrict__ emb,
                            const float* __restrict__ W_ih,
                            const float* __restrict__ W_ihr) {
    float (*As)[16][132] = (float(*)[16][132])(dsm);
    float (*Bs)[16][68]  = (float(*)[16][68])(dsm + 2 * 16 * 132 * 4);
    const int tid = threadIdx.x;
    const int ty = tid >> 4, tx = tid & 15;
    const int m0 = ty << 2, n0 = tx << 2;
    const int ar = tid >> 2, q4 = (tid & 3) << 2;
    const bool bload = (tid < 256);
    const int br = tid >> 2;

    for (int it = 0; it < 8; ++it) {
        int tile = bid + (it << 7);
        int dir = tile >> 9, mt = (tile >> 6) & 7, nt = tile & 63;
        const float* Bw = dir ? W_ihr : W_ih;
        const int m0g = mt << 7, n0g = nt << 6;
        const float* arow = emb + (size_t)(m0g + ar) * 1024 + q4;
        const float* brow = Bw + (size_t)(n0g + br) * 1024 + q4;

        ull acc[2][4];
#pragma unroll
        for (int i = 0; i < 2; i++)
#pragma unroll
            for (int j = 0; j < 4; j++) acc[i][j] = 0ULL;

        float4 pa = __ldg((const float4*)arow);
        float4 pb = make_float4(0.f, 0.f, 0.f, 0.f);
        if (bload) pb = __ldg((const float4*)brow);
        int cur = 0;
        {
            float (*A)[132] = As[0]; float (*B)[68] = Bs[0];
            A[q4+0][ar]=pa.x; A[q4+1][ar]=pa.y; A[q4+2][ar]=pa.z; A[q4+3][ar]=pa.w;
            if (bload) { B[q4+0][br]=pb.x; B[q4+1][br]=pb.y; B[q4+2][br]=pb.z; B[q4+3][br]=pb.w; }
        }
        __syncthreads();
        for (int kk = 0; kk < 64; ++kk) {
            const bool more = (kk + 1) < 64;
            if (more) {
                int k0 = (kk + 1) << 4;
                pa = __ldg((const float4*)(arow + k0));
                if (bload) pb = __ldg((const float4*)(brow + k0));
            }
            {
                const float (*A)[132] = As[cur]; const float (*B)[68] = Bs[cur];
#pragma unroll
                for (int k = 0; k < 16; k++) {
                    const ull* ap = (const ull*)&A[k][m0];
                    ull a0 = ap[0], a1 = ap[1];
                    float4 bv = *(const float4*)&B[k][n0];
                    ull p0=pk2(bv.x,bv.x), p1=pk2(bv.y,bv.y), p2=pk2(bv.z,bv.z), p3=pk2(bv.w,bv.w);
                    fma2(acc[0][0],a0,p0); fma2(acc[0][1],a0,p1); fma2(acc[0][2],a0,p2); fma2(acc[0][3],a0,p3);
                    fma2(acc[1][0],a1,p0); fma2(acc[1][1],a1,p1); fma2(acc[1][2],a1,p2); fma2(acc[1][3],a1,p3);
                }
            }
            if (more) {
                float (*A)[132] = As[cur^1]; float (*B)[68] = Bs[cur^1];
                A[q4+0][ar]=pa.x; A[q4+1][ar]=pa.y; A[q4+2][ar]=pa.z; A[q4+3][ar]=pa.w;
                if (bload) { B[q4+0][br]=pb.x; B[q4+1][br]=pb.y; B[q4+2][br]=pb.z; B[q4+3][br]=pb.w; }
                __syncthreads();
                cur ^= 1;
            }
        }
        __syncthreads();
#pragma unroll
        for (int mp = 0; mp < 2; mp++) {
            int m = m0g + m0 + (mp << 1);
#pragma unroll
            for (int j = 0; j < 4; j++) {
                float2 v = unpk(acc[mp][j]);
                g_P[dir][m][n0g + n0 + j] = v.x;
                g_P[dir][m + 1][n0g + n0 + j] = v.y;
            }
        }
        __syncthreads();
    }
}

// ---------------- HMMA GEMM core: fragment-direct A, 6-buffer B stream -------
// zs[128][66] = A[128, K] @ W^T tile (64 n); A read as pre-built mma fragments;
// B streamed via cp.async into SIX smem buffers, prefetch distance 4,
// issue-early (race-free: buffer (c+4)%6 last read at chunk c-2, fenced by the
// __syncthreads inside iteration c-1).
__device__ __noinline__ void gemm_mma(char* dsm, uint smbB, float (*zs)[66],
    const uint* __restrict__ Af0, const uint* __restrict__ Af1,
    int nch, int nch0,
    const uint4* __restrict__ tb0, const uint4* __restrict__ tb1) {
    const int tid = threadIdx.x;
    const int lane = tid & 31, wid = tid >> 5;
    const int wn = wid & 1, wm = wid >> 1;
    const int lq = lane >> 2, lr = lane & 3;
    uint4* smB = (uint4*)dsm;
    const uint alin = wm * 128 + lane * 4;

    float acc[4][4];
#pragma unroll
    for (int f = 0; f < 4; f++)
#pragma unroll
        for (int k = 0; k < 4; k++) acc[f][k] = 0.0f;

    // B prologue: chunks 0..3 -> buffers 0..3 (always 4 commit groups)
#pragma unroll
    for (int pc = 0; pc < 4; pc++) {
        if (pc < nch) {
            int sg = (pc >= nch0);
            const uint4* s = (sg ? tb1 : tb0) + (size_t)(pc - (sg ? nch0 : 0)) * 1024 + tid;
            uint d = smbB + pc * 16384 + tid * 16;
            CP_ASYNC16(d, s);
            CP_ASYNC16(d + 8192, s + 512);
        }
        CP_COMMIT();
    }
    // A prologue: (c=0, kl=0)
    uint4 cah = __ldcg((const uint4*)(Af0 + alin));
    uint4 cal = __ldcg((const uint4*)(Af0 + 4096 + alin));

    for (int c = 0; c < nch; ++c) {
        // issue B(c+4) early, then wait for B(c)
        if (c + 4 < nch) {
            int cn = c + 4, sg = (cn >= nch0);
            const uint4* s = (sg ? tb1 : tb0) + (size_t)(cn - (sg ? nch0 : 0)) * 1024 + tid;
            uint d = smbB + ((cn % 6) * 16384) + tid * 16;
            CP_ASYNC16(d, s);
            CP_ASYNC16(d + 8192, s + 512);
            CP_COMMIT();
            CP_WAIT4();
        } else if (c + 3 < nch) {
            CP_WAIT3();
        } else if (c + 2 < nch) {
            CP_WAIT2();
        } else if (c + 1 < nch) {
            CP_WAIT1();
        } else {
            CP_WAIT0();
        }
        __syncthreads();

        const uint4* Bb = smB + (c % 6) * 1024;
#pragma unroll
        for (int kl = 0; kl < 4; kl++) {
            uint4 nah, nal;
            const bool hasnext = !((kl == 3) && (c + 1 == nch));
            if (hasnext) {
                int nc = (kl == 3) ? c + 1 : c;
                int nkl = (kl == 3) ? 0 : kl + 1;
                int sg = (nc >= nch0);
                const uint* Afs = (sg ? Af1 : Af0) + (size_t)(nc - (sg ? nch0 : 0)) * 8192;
                nah = __ldcg((const uint4*)(Afs + nkl * 1024 + alin));
                nal = __ldcg((const uint4*)(Afs + 4096 + nkl * 1024 + alin));
            } else {
                nah = cah; nal = cal;
            }
            const uint4* bp = Bb + (kl * 8 + wn * 4) * 32 + lane;
            uint4 B0 = bp[0], B1 = bp[32], B2 = bp[64], B3 = bp[96];
            const uint* ah = (const uint*)&cah;
            const uint* al = (const uint*)&cal;
            MMA_OP(acc[0], ah, B0.x, B0.y); MMA_OP(acc[1], ah, B1.x, B1.y);
            MMA_OP(acc[2], ah, B2.x, B2.y); MMA_OP(acc[3], ah, B3.x, B3.y);
            MMA_OP(acc[0], ah, B0.z, B0.w); MMA_OP(acc[1], ah, B1.z, B1.w);
            MMA_OP(acc[2], ah, B2.z, B2.w); MMA_OP(acc[3], ah, B3.z, B3.w);
            MMA_OP(acc[0], al, B0.x, B0.y); MMA_OP(acc[1], al, B1.x, B1.y);
            MMA_OP(acc[2], al, B2.x, B2.y); MMA_OP(acc[3], al, B3.x, B3.y);
            cah = nah; cal = nal;
        }
    }

    // accumulators -> zs
#pragma unroll
    for (int f = 0; f < 4; f++) {
        int m = wm * 16 + lq;
        int n = wn * 32 + f * 8 + lr * 2;
        *(float2*)&zs[m][n]     = make_float2(acc[f][0], acc[f][1]);
        *(float2*)&zs[m + 8][n] = make_float2(acc[f][2], acc[f][3]);
    }
    __syncthreads();
}

// ---------------- cell epilogue: gates + state + fragment writes --------------
__device__ void cell_epilogue(char* dsm, float (*zs)[66], int layer, int dir,
    int jt, int np, const float* __restrict__ bi, const float* __restrict__ bh,
    uint* __restrict__ hfout, bool dowh) {
    const int tid = threadIdx.x;
    const int j0 = jt << 4;
    uint* hs = (uint*)(dsm + HS_OFF);   // [16][132]
    const int cch = jt >> 2, kl = jt & 3;

#pragma unroll
    for (int it = 0; it < 2; ++it) {
        int item = tid + (it << 9);       // 0..1023
        int b = item >> 3, pk = item & 7;
        int jj0 = pk * 2, jj1 = jj0 + 1;
        int jg0 = j0 + jj0, jg1 = j0 + jj1;
        float z0[4], z1[4];
        z0[0] = zs[b][jj0]      + bi[jg0]        + bh[jg0];
        z0[1] = zs[b][16 + jj0] + bi[1024 + jg0] + bh[1024 + jg0];
        z0[2] = zs[b][32 + jj0] + bi[2048 + jg0] + bh[2048 + jg0];
        z0[3] = zs[b][48 + jj0] + bi[3072 + jg0] + bh[3072 + jg0];
        z1[0] = zs[b][jj1]      + bi[jg1]        + bh[jg1];
        z1[1] = zs[b][16 + jj1] + bi[1024 + jg1] + bh[1024 + jg1];
        z1[2] = zs[b][32 + jj1] + bi[2048 + jg1] + bh[2048 + jg1];
        z1[3] = zs[b][48 + jj1] + bi[3072 + jg1] + bh[3072 + jg1];
        if (layer == 0) {
            int feed = __ldcg(&g_feed[b]);
            const float* pr = &g_P[dir][feed][0];
            z0[0] += pr[jg0]; z0[1] += pr[1024 + jg0]; z0[2] += pr[2048 + jg0]; z0[3] += pr[3072 + jg0];
            z1[0] += pr[jg1]; z1[1] += pr[1024 + jg1]; z1[2] += pr[2048 + jg1]; z1[3] += pr[3072 + jg1];
        }
        uint ps0, ps1;
        {
            float ig = sigf(z0[0]), fg = sigf(z0[1]), gv = tanhf(z0[2]), og = sigf(z0[3]);
            int idx = b * 1024 + jg0;
            float cn = fg * g_c[layer][dir][idx] + ig * gv;
            float hn = og * tanhf(cn);
            g_c[layer][dir][idx] = cn;
            ps0 = pack_split(hn);
        }
        {
            float ig = sigf(z1[0]), fg = sigf(z1[1]), gv = tanhf(z1[2]), og = sigf(z1[3]);
            int idx = b * 1024 + jg1;
            float cn = fg * g_c[layer][dir][idx] + ig * gv;
            float hn = og * tanhf(cn);
            g_c[layer][dir][idx] = cn;
            ps1 = pack_split(hn);
        }
        uint hiU = prmt(ps0, ps1, 0x5410);
        uint loU = prmt(ps0, ps1, 0x7632);
        int slot = ((kl * 8 + (b >> 4)) * 32 + (b & 7) * 4 + (pk & 3)) * 4
                   + ((b >> 3) & 1) + 2 * (pk >> 2);
        hfout[cch * 8192 + slot] = hiU;
        hfout[cch * 8192 + 4096 + slot] = loU;
        if (dowh) {
            hs[jj0 * 132 + b] = ps0;
            hs[jj1 * 132 + b] = ps1;
        }
    }
    if (dowh) {
        __syncthreads();
#pragma unroll
        for (int it = 0; it < 2; ++it) {
            int item = tid + (it << 9);
            int ccl = item >> 6, bp = item & 63;
            int b0 = bp * 2, b1 = b0 + 1;
            uint psa = hs[ccl * 132 + b0], psb = hs[ccl * 132 + b1];
            uint hiU = prmt(psa, psb, 0x5410), loU = prmt(psa, psb, 0x7632);
            int cc = (dir << 10) + (jt << 4) + ccl;
            int b2 = cc >> 4;
            int j2 = ((cc & 15) << 7) + b0;   // even
            int c2 = j2 >> 6;
            int slot = frag_slot(b2, j2);
            g_whf[c2 * 8192 + slot] = hiU;
            g_whf[c2 * 8192 + 4096 + slot] = loU;
        }
    }
}

// ---------------- fc epilogue --------------------------------------------------
__device__ __forceinline__ void fc_epilogue(float (*zs)[66], int et, int ks2) {
    const int tid = threadIdx.x;
    const int b = tid >> 2, n0 = (tid & 3) << 4;
    float* lp = &g_logitsP[ks2][b * 1024 + et * 64 + n0];
#pragma unroll
    for (int j = 0; j < 16; j++) lp[j] = zs[b][n0 + j];
}

// ---------------- final phase --------------------------------------------------
__device__ void final_phase(char* dsm, int bid, const float* __restrict__ fc_b,
                            float* __restrict__ out, int t) {
    const int b = bid;
    const int tid = threadIdx.x;
    float* sl = (float*)(dsm + ZS_OFF);
    float* sv = sl + 1024;
    int*   si = (int*)(sl + 1536);
    float* ssum = sl + 2048;

    const int end = __ldcg(&g_ended[b]);
    float bv = -3.402823466e38f;
    int bidx = 0;
    for (int e = tid; e < 1024; e += NTHR) {
        float v;
        if (end) {
            v = (e == 1) ? 1.0f : 0.0f;
        } else {
            v = fc_b[e];
#pragma unroll
            for (int s = 0; s < 8; s++) v += __ldcg(&g_logitsP[s][b * 1024 + e]);
        }
        sl[e] = v;
        if (v > bv) { bv = v; bidx = e; }
    }
    sv[tid] = bv; si[tid] = bidx;
    __syncthreads();
    for (int s = NTHR / 2; s > 0; s >>= 1) {
        if (tid < s) {
            float v2 = sv[tid + s]; int i2 = si[tid + s];
            if (v2 > sv[tid] || (v2 == sv[tid] && i2 < si[tid])) { sv[tid] = v2; si[tid] = i2; }
        }
        __syncthreads();
    }
    float mx = sv[0];
    int label = si[0];
    __syncthreads();

    float ps = 0.0f;
    for (int e = tid; e < 1024; e += NTHR) ps += expf(sl[e] - mx);
    ssum[tid] = ps;
    __syncthreads();
    for (int s = NTHR / 2; s > 0; s >>= 1) {
        if (tid < s) ssum[tid] += ssum[tid + s];
        __syncthreads();
    }
    float inv = 1.0f / ssum[0];

    float* orow = out + ((size_t)b * TSTEPS + t) * 1024;
    for (int e = tid; e < 1024; e += NTHR) orow[e] = expf(sl[e] - mx) * inv;

    if (tid == 0) {
        g_feed[b] = label;
        g_ended[b] = end | (label == 1);  // EOS = 1
    }
}

// ---------------- mega kernel --------------------------------------------------
__global__ void __launch_bounds__(NTHR, 1) main_kernel(
    const int* __restrict__ yy,
    const float* __restrict__ h_t, const float* __restrict__ h_tr,
    const float* __restrict__ c0, const float* __restrict__ c0r,
    const float* __restrict__ emb,
    const float* __restrict__ W_ih, const float* __restrict__ W_hh,
    const float* __restrict__ b_ih, const float* __restrict__ b_hh,
    const float* __restrict__ W_ihr, const float* __restrict__ W_hhr,
    const float* __restrict__ b_ihr, const float* __restrict__ b_hhr,
    const float* __restrict__ fcW, const float* __restrict__ fc_b,
    float* __restrict__ out) {
    extern __shared__ char dsm[];
    const uint smbB = s2u(dsm);
    float (*zs)[66] = (float(*)[66])(dsm + ZS_OFF);
    const int bid = blockIdx.x;

    init_phase(bid, yy, h_t, h_tr, c0, c0r);
    setup_weights(bid, W_ih, W_hh, W_ihr, W_hhr, fcW);
    pcomp_phase(dsm, bid, emb, W_ih, W_ihr);
    gbar();

    const int dir = bid >> 6;
    const int jt = bid & 63;
    const int et = bid >> 3;
    const int ks2 = bid & 7;
    const float* bi0 = (dir ? b_ihr : b_ih);
    const float* bh0 = (dir ? b_hhr : b_hh);
    const float* bi1 = bi0 + 4096;
    const float* bh1 = bh0 + 4096;
    const uint4* tL0  = g_WB + (size_t)((dir * 3 + 0) * 64 + jt) * 16384;
    const uint4* tL1a = g_WB + (size_t)((dir * 3 + 1) * 64 + jt) * 16384;
    const uint4* tL1b = g_WB + (size_t)((dir * 3 + 2) * 64 + jt) * 16384;
    const uint4* tFC  = g_WB + CELL_SLOTS + (size_t)(et * 8 + ks2) * 4096;

    for (int t = 0; t < TSTEPS; ++t) {
        const int p = t & 1;
        const int np = p ^ 1;
        // layer 0: z = h0_prev @ Whh0^T (+ P[feed] in epilogue)
        gemm_mma(dsm, smbB, zs, g_hf[0][dir][p], g_hf[0][dir][p], 16, 16, tL0, tL0);
        cell_epilogue(dsm, zs, 0, dir, jt, np, bi0, bh0, g_hf[0][dir][np], false);
        gbar();
        // layer 1: z = h0_new @ Wih1^T + h1_prev @ Whh1^T
        gemm_mma(dsm, smbB, zs, g_hf[0][dir][np], g_hf[1][dir][p], 32, 16, tL1a, tL1b);
        cell_epilogue(dsm, zs, 1, dir, jt, np, bi1, bh1, g_hf[1][dir][np], true);
        gbar();
        // fc: logits partial, K slice ks2*256..+256 (wh fragment chunks ks2*4..+4)
        gemm_mma(dsm, smbB, zs, g_whf + (size_t)(ks2 * 4) * 8192,
                 g_whf, 4, 4, tFC, tFC);
        fc_epilogue(zs, et, ks2);
        gbar();
        final_phase(dsm, bid, fc_b, out, t);
        gbar();
    }
}

// ---------------- launch --------------------------------------------------------
extern "C" void kernel_launch(void* const* d_in, const int* in_sizes, int n_in,
                              void* d_out, int out_size) {
    const int* yy = (const int*)d_in[0];
    const float* h_t = (const float*)d_in[1];
    const float* h_tr = (const float*)d_in[2];
    // d_in[3] = x_lens (unused by the reference computation)
    const float* emb = (const float*)d_in[4];
    const float* W_ih = (const float*)d_in[5];
    const float* W_hh = (const float*)d_in[6];
    const float* b_ih = (const float*)d_in[7];
    const float* b_hh = (const float*)d_in[8];
    const float* W_ihr = (const float*)d_in[9];
    const float* W_hhr = (const float*)d_in[10];
    const float* b_ihr = (const float*)d_in[11];
    const float* b_hhr = (const float*)d_in[12];
    const float* c0 = (const float*)d_in[13];
    const float* c0r = (const float*)d_in[14];
    const float* fc_W = (const float*)d_in[15];
    const float* fc_b = (const float*)d_in[16];
    float* out = (float*)d_out;

    cudaFuncSetAttribute(main_kernel, cudaFuncAttributeMaxDynamicSharedMemorySize, SMEM_BYTES);
    main_kernel<<<NBLK, NTHR, SMEM_BYTES>>>(yy, h_t, h_tr, c0, c0r, emb,
                                            W_ih, W_hh, b_ih, b_hh,
                                            W_ihr, W_hhr, b_ihr, b_hhr,
                                            fc_W, fc_b, out);
}

// round 16
// speedup vs baseline: 1.1339x; 1.1339x over previous
#include <cuda_runtime.h>
#include <cuda_bf16.h>
#include <math.h>

typedef unsigned long long ull;
typedef unsigned int uint;

#define BATCH  128
#define TSTEPS 256
#define NBLK   128
#define NTHR   256

#define CELL_SLOTS 6291456u            // 384 tiles * 16384 uint4 slots
#define FC_SLOTS   524288u             // 128 tiles * 4096
#define TOT_SLOTS  (CELL_SLOTS + FC_SLOTS)

// dynamic smem map (bytes):
// four 48 KB stream buffers: [B 16KB | A-hi 16KB | A-lo 16KB] each
//   buffer i at i*49152, i = 0..3
// zs[128][66] + hs[16][132] + final scratch live in buffer 3's space
//   (only touched after gemm-end WAIT0+sync; next gemm writes buf3 only
//    after the intervening grid barrier)
#define BUF_BYTES 49152
#define ZS_OFF    147456               // = 3*49152
#define HS_OFF    181248               // = ZS_OFF + 33792
#define SMEM_BYTES 196608

// ---------------- device scratch -------------------------------------------
__device__ float g_P[2][1024][4096];            // emb @ W_ih(l0)^T, fp32
__device__ float g_c[2][2][BATCH * 1024];
__device__ float g_logitsP[8][BATCH * 1024];    // split-K partials
__device__ int   g_feed[BATCH];
__device__ int   g_ended[BATCH];
__device__ unsigned g_cnt = 0, g_gen = 0;
__device__ uint4 g_WB[TOT_SLOTS];               // pre-fragmented split-bf16 weights
// A in mma-fragment layout: per 64-K chunk = 8192 uints (hi plane 4096 | lo plane 4096)
__device__ __align__(16) uint g_hf[2][2][2][16 * 8192];  // [layer][dir][buf]
__device__ __align__(16) uint g_whf[32 * 8192];          // scrambled fc input

// ---------------- helpers ----------------------------------------------------
__device__ __forceinline__ uint prmt(uint a, uint b, uint s) {
    uint r; asm("prmt.b32 %0, %1, %2, %3;" : "=r"(r) : "r"(a), "r"(b), "r"(s));
    return r;
}
__device__ __forceinline__ uint b2u(__nv_bfloat162 v) { return *reinterpret_cast<uint*>(&v); }
__device__ __forceinline__ uint pack_split(float v) {
    __nv_bfloat16 h = __float2bfloat16_rn(v);
    float hf = __bfloat162float(h);
    __nv_bfloat16 l = __float2bfloat16_rn(v - hf);
    return (uint)__bfloat16_as_ushort(h) | ((uint)__bfloat16_as_ushort(l) << 16);
}
__device__ __forceinline__ float sigf(float x) { return 1.0f / (1.0f + expf(-x)); }
__device__ __forceinline__ uint s2u(const void* p) {
    uint a;
    asm("{ .reg .u64 t; cvta.to.shared.u64 t, %1; cvt.u32.u64 %0, t; }" : "=r"(a) : "l"(p));
    return a;
}
// fragment slot for value pair (b-row, even j): uint index within an 8192-uint chunk
__device__ __forceinline__ int frag_slot(int brow, int j) {
    int kl = (j >> 4) & 3, pk = (j >> 1) & 7;
    return ((kl * 8 + (brow >> 4)) * 32 + (brow & 7) * 4 + (pk & 3)) * 4
           + ((brow >> 3) & 1) + 2 * (pk >> 2);
}

#define MMA_OP(d, a, bb0, bb1) \
    asm volatile( \
        "mma.sync.aligned.m16n8k16.row.col.f32.bf16.bf16.f32 " \
        "{%0,%1,%2,%3}, {%4,%5,%6,%7}, {%8,%9}, {%0,%1,%2,%3};" \
        : "+f"((d)[0]), "+f"((d)[1]), "+f"((d)[2]), "+f"((d)[3]) \
        : "r"((a)[0]), "r"((a)[1]), "r"((a)[2]), "r"((a)[3]), "r"(bb0), "r"(bb1))

#define CP_ASYNC16(daddr, saddr) \
    asm volatile("cp.async.cg.shared.global [%0], [%1], 16;" :: "r"(daddr), "l"(saddr) : "memory")
#define CP_COMMIT() asm volatile("cp.async.commit_group;" ::: "memory")
#define CP_WAIT2()  asm volatile("cp.async.wait_group 2;" ::: "memory")
#define CP_WAIT1()  asm volatile("cp.async.wait_group 1;" ::: "memory")
#define CP_WAIT0()  asm volatile("cp.async.wait_group 0;" ::: "memory")

// ---------------- f32x2 helpers (pcomp only) --------------------------------
__device__ __forceinline__ ull pk2(float lo, float hi) {
    ull r; asm("mov.b64 %0, {%1,%2};" : "=l"(r) : "f"(lo), "f"(hi)); return r;
}
__device__ __forceinline__ void fma2(ull& d, ull a, ull b) {
    asm("fma.rn.f32x2 %0, %1, %2, %0;" : "+l"(d) : "l"(a), "l"(b));
}
__device__ __forceinline__ float2 unpk(ull v) {
    float2 r; asm("mov.b64 {%0,%1}, %2;" : "=f"(r.x), "=f"(r.y) : "l"(v)); return r;
}

// ---------------- software grid barrier --------------------------------------
__device__ __forceinline__ void gbar() {
    __threadfence();
    __syncthreads();
    if (threadIdx.x == 0) {
        unsigned gen = atomicAdd(&g_gen, 0u);
        unsigned arrived = atomicAdd(&g_cnt, 1u);
        if (arrived == NBLK - 1u) {
            atomicExch(&g_cnt, 0u);
            __threadfence();
            atomicAdd(&g_gen, 1u);
        } else {
            while (atomicAdd(&g_gen, 0u) == gen) { __nanosleep(64); }
        }
        __threadfence();
    }
    __syncthreads();
}

// ---------------- init: h fragments + c + feed --------------------------------
__device__ void init_phase(int bid, const int* __restrict__ yy,
                           const float* __restrict__ h_t,
                           const float* __restrict__ h_tr,
                           const float* __restrict__ c0,
                           const float* __restrict__ c0r) {
    const int gid0 = bid * NTHR + threadIdx.x;
    const int LBH = BATCH * 1024;
    for (int i = gid0; i < 2 * 2 * 128 * 512; i += NBLK * NTHR) {
        int l = i >> 17;
        int rem = i & 131071;
        int dr = rem >> 16;
        int rem2 = rem & 65535;
        int b = rem2 >> 9;
        int pj = rem2 & 511;
        int j = pj * 2;
        const float* src = (dr ? h_tr : h_t) + (size_t)l * LBH + b * 1024 + j;
        uint ps0 = pack_split(src[0]);
        uint ps1 = pack_split(src[1]);
        uint hiU = prmt(ps0, ps1, 0x5410), loU = prmt(ps0, ps1, 0x7632);
        int cch = j >> 6;
        int slot = frag_slot(b, j);
        uint* hf = &g_hf[l][dr][0][0];
        hf[cch * 8192 + slot] = hiU;
        hf[cch * 8192 + 4096 + slot] = loU;
    }
    for (int i = gid0; i < 2 * LBH; i += NBLK * NTHR) {
        int l = i / LBH, r = i % LBH, j = r & 1023;
        g_c[l][0][r] = c0[l * 1024 + j];
        g_c[l][1][r] = c0r[l * 1024 + j];
    }
    if (bid == 0 && threadIdx.x < BATCH) {
        g_feed[threadIdx.x] = yy[threadIdx.x * TSTEPS];
        g_ended[threadIdx.x] = 0;
    }
}

// ---------------- setup: split + pre-fragment weights ------------------------
__device__ void setup_weights(int bid,
    const float* __restrict__ W_ih, const float* __restrict__ W_hh,
    const float* __restrict__ W_ihr, const float* __restrict__ W_hhr,
    const float* __restrict__ fcW) {
    for (uint s = bid * NTHR + threadIdx.x; s < TOT_SLOTS; s += NBLK * NTHR) {
        const float* p;
        if (s < CELL_SLOTS) {
            uint tile = s >> 14, rem = s & 16383u;
            uint ks = rem >> 8, nf = (rem >> 5) & 7, lane = rem & 31;
            uint dir = tile / 192, seg = (tile / 64) % 3, jt = tile & 63;
            const float* W;
            if (seg == 0)      W = dir ? W_hhr : W_hh;
            else if (seg == 1) W = (dir ? W_ihr : W_ih) + (size_t)4096 * 1024;
            else               W = (dir ? W_hhr : W_hh) + (size_t)4096 * 1024;
            uint n = nf * 8 + (lane >> 2);
            uint row = (n >> 4) * 1024 + jt * 16 + (n & 15);
            uint kb = ks * 16 + (lane & 3) * 2;
            p = W + (size_t)row * 1024 + kb;
        } else {
            uint srel = s - CELL_SLOTS;
            uint f = srel >> 12, rem = srel & 4095u;
            uint ks = rem >> 8, nf = (rem >> 5) & 7, lane = rem & 31;
            uint et = f >> 3, ks2 = f & 7;
            uint n = nf * 8 + (lane >> 2);
            uint row = et * 64 + n;
            uint kb = ks2 * 256 + ks * 16 + (lane & 3) * 2;
            p = fcW + (size_t)row * 2048 + kb;
        }
        float2 r01 = __ldg((const float2*)p);
        float2 r89 = __ldg((const float2*)(p + 8));
        __nv_bfloat162 H01 = __floats2bfloat162_rn(r01.x, r01.y);
        __nv_bfloat162 H89 = __floats2bfloat162_rn(r89.x, r89.y);
        __nv_bfloat162 L01 = __floats2bfloat162_rn(r01.x - __bfloat162float(H01.x),
                                                   r01.y - __bfloat162float(H01.y));
        __nv_bfloat162 L89 = __floats2bfloat162_rn(r89.x - __bfloat162float(H89.x),
                                                   r89.y - __bfloat162float(H89.y));
        g_WB[s] = make_uint4(b2u(H01), b2u(H89), b2u(L01), b2u(L89));
    }
}

// ---------------- pcomp (fp32 f32x2, 256 thr): P = emb @ W_ih(l0)^T ----------
__device__ void pcomp_phase(char* dsm, int bid, const float* __restrict__ emb,
                            const float* __restrict__ W_ih,
                            const float* __restrict__ W_ihr) {
    float (*As)[16][132] = (float(*)[16][132])(dsm);
    float (*Bs)[16][68]  = (float(*)[16][68])(dsm + 2 * 16 * 132 * 4);
    const int tid = threadIdx.x;
    const int ty = tid >> 4, tx = tid & 15;
    const int m0 = ty << 3, n0 = tx << 2;
    const int r = tid >> 2, q4 = (tid & 3) << 2;

    for (int it = 0; it < 8; ++it) {
        int tile = bid + (it << 7);
        int dir = tile >> 9, mt = (tile >> 6) & 7, nt = tile & 63;
        const float* Bw = dir ? W_ihr : W_ih;
        const int m0g = mt << 7, n0g = nt << 6;
        const float* arow0 = emb + (size_t)(m0g + r) * 1024 + q4;
        const float* arow1 = emb + (size_t)(m0g + r + 64) * 1024 + q4;
        const float* brow  = Bw + (size_t)(n0g + r) * 1024 + q4;

        ull acc[4][4];
#pragma unroll
        for (int i = 0; i < 4; i++)
#pragma unroll
            for (int j = 0; j < 4; j++) acc[i][j] = 0ULL;

        float4 pa0 = __ldg((const float4*)arow0);
        float4 pa1 = __ldg((const float4*)arow1);
        float4 pb  = __ldg((const float4*)brow);
        int cur = 0;
        {
            float (*A)[132] = As[0]; float (*B)[68] = Bs[0];
            A[q4+0][r]=pa0.x; A[q4+1][r]=pa0.y; A[q4+2][r]=pa0.z; A[q4+3][r]=pa0.w;
            A[q4+0][r+64]=pa1.x; A[q4+1][r+64]=pa1.y; A[q4+2][r+64]=pa1.z; A[q4+3][r+64]=pa1.w;
            B[q4+0][r]=pb.x; B[q4+1][r]=pb.y; B[q4+2][r]=pb.z; B[q4+3][r]=pb.w;
        }
        __syncthreads();
        for (int kk = 0; kk < 64; ++kk) {
            const bool more = (kk + 1) < 64;
            if (more) {
                int k0 = (kk + 1) << 4;
                pa0 = __ldg((const float4*)(arow0 + k0));
                pa1 = __ldg((const float4*)(arow1 + k0));
                pb  = __ldg((const float4*)(brow + k0));
            }
            {
                const float (*A)[132] = As[cur]; const float (*B)[68] = Bs[cur];
#pragma unroll
                for (int k = 0; k < 16; k++) {
                    const ull* ap = (const ull*)&A[k][m0];
                    ull a0=ap[0], a1=ap[1], a2=ap[2], a3=ap[3];
                    float4 bv = *(const float4*)&B[k][n0];
                    ull p0=pk2(bv.x,bv.x), p1=pk2(bv.y,bv.y), p2=pk2(bv.z,bv.z), p3=pk2(bv.w,bv.w);
                    fma2(acc[0][0],a0,p0); fma2(acc[0][1],a0,p1); fma2(acc[0][2],a0,p2); fma2(acc[0][3],a0,p3);
                    fma2(acc[1][0],a1,p0); fma2(acc[1][1],a1,p1); fma2(acc[1][2],a1,p2); fma2(acc[1][3],a1,p3);
                    fma2(acc[2][0],a2,p0); fma2(acc[2][1],a2,p1); fma2(acc[2][2],a2,p2); fma2(acc[2][3],a2,p3);
                    fma2(acc[3][0],a3,p0); fma2(acc[3][1],a3,p1); fma2(acc[3][2],a3,p2); fma2(acc[3][3],a3,p3);
                }
            }
            if (more) {
                float (*A)[132] = As[cur^1]; float (*B)[68] = Bs[cur^1];
                A[q4+0][r]=pa0.x; A[q4+1][r]=pa0.y; A[q4+2][r]=pa0.z; A[q4+3][r]=pa0.w;
                A[q4+0][r+64]=pa1.x; A[q4+1][r+64]=pa1.y; A[q4+2][r+64]=pa1.z; A[q4+3][r+64]=pa1.w;
                B[q4+0][r]=pb.x; B[q4+1][r]=pb.y; B[q4+2][r]=pb.z; B[q4+3][r]=pb.w;
                __syncthreads();
                cur ^= 1;
            }
        }
        __syncthreads();
#pragma unroll
        for (int mp = 0; mp < 4; mp++) {
            int m = m0g + m0 + (mp << 1);
#pragma unroll
            for (int j = 0; j < 4; j++) {
                float2 v = unpk(acc[mp][j]);
                g_P[dir][m][n0g + n0 + j] = v.x;
                g_P[dir][m + 1][n0g + n0 + j] = v.y;
            }
        }
        __syncthreads();
    }
}

// ---------------- HMMA GEMM core: A+B streamed, 32x32 warp tiles -------------
// 8 warps: wm = wid&3 (32 m rows), wn = wid>>2 (32 n cols).
// Chunk buffer (48KB): B uint[0,4096) | A-hi uint[4096,8192) | A-lo [8192,12288).
// 4 buffers, prefetch distance 2, issue-early (buffer (c+2)&3 last read at
// chunk c-2, fenced by iteration c-1's __syncthreads -> race-free).
__device__ __forceinline__ void stream_issue(uint smb, int cn, int nch0,
    const uint* __restrict__ Af0, const uint* __restrict__ Af1,
    const uint4* __restrict__ tb0, const uint4* __restrict__ tb1, int tid) {
    int sg = (cn >= nch0);
    int cl = cn - (sg ? nch0 : 0);
    const uint4* bs = (sg ? tb1 : tb0) + (size_t)cl * 1024 + tid;
    const uint4* as = (const uint4*)((sg ? Af1 : Af0) + (size_t)cl * 8192) + tid;
    uint d = smb + (cn & 3) * BUF_BYTES + tid * 16;
#pragma unroll
    for (int i = 0; i < 4; i++) CP_ASYNC16(d + i * 4096, bs + i * 256);
    uint dA = d + 16384;
#pragma unroll
    for (int i = 0; i < 8; i++) CP_ASYNC16(dA + i * 4096, as + i * 256);
    CP_COMMIT();
}

__device__ __noinline__ void gemm_mma(char* dsm, uint smb, float (*zs)[66],
    const uint* __restrict__ Af0, const uint* __restrict__ Af1,
    int nch, int nch0,
    const uint4* __restrict__ tb0, const uint4* __restrict__ tb1) {
    const int tid = threadIdx.x;
    const int lane = tid & 31, wid = tid >> 5;
    const int wm = wid & 3, wn = wid >> 2;
    const int lq = lane >> 2, lr = lane & 3;

    float acc[2][4][4];
#pragma unroll
    for (int mf = 0; mf < 2; mf++)
#pragma unroll
        for (int f = 0; f < 4; f++)
#pragma unroll
            for (int k = 0; k < 4; k++) acc[mf][f][k] = 0.0f;

    stream_issue(smb, 0, nch0, Af0, Af1, tb0, tb1, tid);
    stream_issue(smb, 1, nch0, Af0, Af1, tb0, tb1, tid);

    const int aoff = wm * 256 + lane * 4;

    for (int c = 0; c < nch; ++c) {
        if (c + 2 < nch) {
            stream_issue(smb, c + 2, nch0, Af0, Af1, tb0, tb1, tid);
            CP_WAIT2();
        } else if (c + 1 < nch) {
            CP_WAIT1();
        } else {
            CP_WAIT0();
        }
        __syncthreads();

        const uint* Bu = (const uint*)(dsm + (c & 3) * BUF_BYTES);
        const uint* Au = Bu + 4096;
#pragma unroll
        for (int kl = 0; kl < 4; kl++) {
            const uint4* bp = (const uint4*)Bu + (kl * 8 + wn * 4) * 32 + lane;
            uint4 B0 = bp[0], B1 = bp[32], B2 = bp[64], B3 = bp[96];
            int base = kl * 1024 + aoff;
            uint4 aH0 = *(const uint4*)(Au + base);
            uint4 aH1 = *(const uint4*)(Au + base + 128);
            uint4 aL0 = *(const uint4*)(Au + 4096 + base);
            uint4 aL1 = *(const uint4*)(Au + 4096 + base + 128);
            const uint* h0 = (const uint*)&aH0;
            const uint* h1 = (const uint*)&aH1;
            const uint* l0 = (const uint*)&aL0;
            const uint* l1 = (const uint*)&aL1;
            // product-major (per-acc order stays hh, hl, lh -> bitwise same)
            MMA_OP(acc[0][0], h0, B0.x, B0.y); MMA_OP(acc[0][1], h0, B1.x, B1.y);
            MMA_OP(acc[0][2], h0, B2.x, B2.y); MMA_OP(acc[0][3], h0, B3.x, B3.y);
            MMA_OP(acc[1][0], h1, B0.x, B0.y); MMA_OP(acc[1][1], h1, B1.x, B1.y);
            MMA_OP(acc[1][2], h1, B2.x, B2.y); MMA_OP(acc[1][3], h1, B3.x, B3.y);
            MMA_OP(acc[0][0], h0, B0.z, B0.w); MMA_OP(acc[0][1], h0, B1.z, B1.w);
            MMA_OP(acc[0][2], h0, B2.z, B2.w); MMA_OP(acc[0][3], h0, B3.z, B3.w);
            MMA_OP(acc[1][0], h1, B0.z, B0.w); MMA_OP(acc[1][1], h1, B1.z, B1.w);
            MMA_OP(acc[1][2], h1, B2.z, B2.w); MMA_OP(acc[1][3], h1, B3.z, B3.w);
            MMA_OP(acc[0][0], l0, B0.x, B0.y); MMA_OP(acc[0][1], l0, B1.x, B1.y);
            MMA_OP(acc[0][2], l0, B2.x, B2.y); MMA_OP(acc[0][3], l0, B3.x, B3.y);
            MMA_OP(acc[1][0], l1, B0.x, B0.y); MMA_OP(acc[1][1], l1, B1.x, B1.y);
            MMA_OP(acc[1][2], l1, B2.x, B2.y); MMA_OP(acc[1][3], l1, B3.x, B3.y);
        }
    }

    // zs lives in buffer 3's space and the last chunk reads buffer 3 ->
    // must fence ALL warps' reads before overwriting.
    __syncthreads();
#pragma unroll
    for (int mf = 0; mf < 2; mf++)
#pragma unroll
        for (int f = 0; f < 4; f++) {
            int m = wm * 32 + mf * 16 + lq;
            int n = wn * 32 + f * 8 + lr * 2;
            *(float2*)&zs[m][n]     = make_float2(acc[mf][f][0], acc[mf][f][1]);
            *(float2*)&zs[m + 8][n] = make_float2(acc[mf][f][2], acc[mf][f][3]);
        }
    __syncthreads();
}

// ---------------- cell epilogue: gates + state + fragment writes --------------
__device__ void cell_epilogue(char* dsm, float (*zs)[66], int layer, int dir,
    int jt, int np, const float* __restrict__ bi, const float* __restrict__ bh,
    uint* __restrict__ hfout, bool dowh) {
    const int tid = threadIdx.x;
    const int j0 = jt << 4;
    uint* hs = (uint*)(dsm + HS_OFF);   // [16][132]
    const int cch = jt >> 2, kl = jt & 3;

#pragma unroll
    for (int it = 0; it < 4; ++it) {
        int item = tid + (it << 8);       // 0..1023
        int b = item >> 3, pk = item & 7;
        int jj0 = pk * 2, jj1 = jj0 + 1;
        int jg0 = j0 + jj0, jg1 = j0 + jj1;
        float z0[4], z1[4];
        z0[0] = zs[b][jj0]      + bi[jg0]        + bh[jg0];
        z0[1] = zs[b][16 + jj0] + bi[1024 + jg0] + bh[1024 + jg0];
        z0[2] = zs[b][32 + jj0] + bi[2048 + jg0] + bh[2048 + jg0];
        z0[3] = zs[b][48 + jj0] + bi[3072 + jg0] + bh[3072 + jg0];
        z1[0] = zs[b][jj1]      + bi[jg1]        + bh[jg1];
        z1[1] = zs[b][16 + jj1] + bi[1024 + jg1] + bh[1024 + jg1];
        z1[2] = zs[b][32 + jj1] + bi[2048 + jg1] + bh[2048 + jg1];
        z1[3] = zs[b][48 + jj1] + bi[3072 + jg1] + bh[3072 + jg1];
        if (layer == 0) {
            int feed = __ldcg(&g_feed[b]);
            const float* pr = &g_P[dir][feed][0];
            z0[0] += pr[jg0]; z0[1] += pr[1024 + jg0]; z0[2] += pr[2048 + jg0]; z0[3] += pr[3072 + jg0];
            z1[0] += pr[jg1]; z1[1] += pr[1024 + jg1]; z1[2] += pr[2048 + jg1]; z1[3] += pr[3072 + jg1];
        }
        uint ps0, ps1;
        {
            float ig = sigf(z0[0]), fg = sigf(z0[1]), gv = tanhf(z0[2]), og = sigf(z0[3]);
            int idx = b * 1024 + jg0;
            float cn = fg * g_c[layer][dir][idx] + ig * gv;
            float hn = og * tanhf(cn);
            g_c[layer][dir][idx] = cn;
            ps0 = pack_split(hn);
        }
        {
            float ig = sigf(z1[0]), fg = sigf(z1[1]), gv = tanhf(z1[2]), og = sigf(z1[3]);
            int idx = b * 1024 + jg1;
            float cn = fg * g_c[layer][dir][idx] + ig * gv;
            float hn = og * tanhf(cn);
            g_c[layer][dir][idx] = cn;
            ps1 = pack_split(hn);
        }
        uint hiU = prmt(ps0, ps1, 0x5410);
        uint loU = prmt(ps0, ps1, 0x7632);
        int slot = ((kl * 8 + (b >> 4)) * 32 + (b & 7) * 4 + (pk & 3)) * 4
                   + ((b >> 3) & 1) + 2 * (pk >> 2);
        hfout[cch * 8192 + slot] = hiU;
        hfout[cch * 8192 + 4096 + slot] = loU;
        if (dowh) {
            hs[jj0 * 132 + b] = ps0;
            hs[jj1 * 132 + b] = ps1;
        }
    }
    if (dowh) {
        __syncthreads();
#pragma unroll
        for (int it = 0; it < 4; ++it) {
            int item = tid + (it << 8);
            int ccl = item >> 6, bp = item & 63;
            int b0 = bp * 2, b1 = b0 + 1;
            uint psa = hs[ccl * 132 + b0], psb = hs[ccl * 132 + b1];
            uint hiU = prmt(psa, psb, 0x5410), loU = prmt(psa, psb, 0x7632);
            int cc = (dir << 10) + (jt << 4) + ccl;
            int b2 = cc >> 4;
            int j2 = ((cc & 15) << 7) + b0;   // even
            int c2 = j2 >> 6;
            int slot = frag_slot(b2, j2);
            g_whf[c2 * 8192 + slot] = hiU;
            g_whf[c2 * 8192 + 4096 + slot] = loU;
        }
    }
}

// ---------------- fc epilogue --------------------------------------------------
__device__ __forceinline__ void fc_epilogue(float (*zs)[66], int et, int ks2) {
    const int tid = threadIdx.x;
    const int b = tid >> 1, n0 = (tid & 1) << 5;
    float* lp = &g_logitsP[ks2][b * 1024 + et * 64 + n0];
#pragma unroll
    for (int j = 0; j < 32; j++) lp[j] = zs[b][n0 + j];
}

// ---------------- final phase --------------------------------------------------
__device__ void final_phase(char* dsm, int bid, const float* __restrict__ fc_b,
                            float* __restrict__ out, int t) {
    const int b = bid;
    const int tid = threadIdx.x;
    float* sl = (float*)(dsm + ZS_OFF);
    float* sv = sl + 1024;
    int*   si = (int*)(sl + 1280);
    float* ssum = sl + 1536;

    const int end = __ldcg(&g_ended[b]);
    float bv = -3.402823466e38f;
    int bidx = 0;
    for (int e = tid; e < 1024; e += NTHR) {
        float v;
        if (end) {
            v = (e == 1) ? 1.0f : 0.0f;
        } else {
            v = fc_b[e];
#pragma unroll
            for (int s = 0; s < 8; s++) v += __ldcg(&g_logitsP[s][b * 1024 + e]);
        }
        sl[e] = v;
        if (v > bv) { bv = v; bidx = e; }
    }
    sv[tid] = bv; si[tid] = bidx;
    __syncthreads();
    for (int s = NTHR / 2; s > 0; s >>= 1) {
        if (tid < s) {
            float v2 = sv[tid + s]; int i2 = si[tid + s];
            if (v2 > sv[tid] || (v2 == sv[tid] && i2 < si[tid])) { sv[tid] = v2; si[tid] = i2; }
        }
        __syncthreads();
    }
    float mx = sv[0];
    int label = si[0];
    __syncthreads();

    float ps = 0.0f;
    for (int e = tid; e < 1024; e += NTHR) ps += expf(sl[e] - mx);
    ssum[tid] = ps;
    __syncthreads();
    for (int s = NTHR / 2; s > 0; s >>= 1) {
        if (tid < s) ssum[tid] += ssum[tid + s];
        __syncthreads();
    }
    float inv = 1.0f / ssum[0];

    float* orow = out + ((size_t)b * TSTEPS + t) * 1024;
    for (int e = tid; e < 1024; e += NTHR) orow[e] = expf(sl[e] - mx) * inv;

    if (tid == 0) {
        g_feed[b] = label;
        g_ended[b] = end | (label == 1);  // EOS = 1
    }
}

// ---------------- mega kernel --------------------------------------------------
__global__ void __launch_bounds__(NTHR, 1) main_kernel(
    const int* __restrict__ yy,
    const float* __restrict__ h_t, const float* __restrict__ h_tr,
    const float* __restrict__ c0, const float* __restrict__ c0r,
    const float* __restrict__ emb,
    const float* __restrict__ W_ih, const float* __restrict__ W_hh,
    const float* __restrict__ b_ih, const float* __restrict__ b_hh,
    const float* __restrict__ W_ihr, const float* __restrict__ W_hhr,
    const float* __restrict__ b_ihr, const float* __restrict__ b_hhr,
    const float* __restrict__ fcW, const float* __restrict__ fc_b,
    float* __restrict__ out) {
    extern __shared__ char dsm[];
    const uint smb = s2u(dsm);
    float (*zs)[66] = (float(*)[66])(dsm + ZS_OFF);
    const int bid = blockIdx.x;

    init_phase(bid, yy, h_t, h_tr, c0, c0r);
    setup_weights(bid, W_ih, W_hh, W_ihr, W_hhr, fcW);
    pcomp_phase(dsm, bid, emb, W_ih, W_ihr);
    gbar();

    const int dir = bid >> 6;
    const int jt = bid & 63;
    const int et = bid >> 3;
    const int ks2 = bid & 7;
    const float* bi0 = (dir ? b_ihr : b_ih);
    const float* bh0 = (dir ? b_hhr : b_hh);
    const float* bi1 = bi0 + 4096;
    const float* bh1 = bh0 + 4096;
    const uint4* tL0  = g_WB + (size_t)((dir * 3 + 0) * 64 + jt) * 16384;
    const uint4* tL1a = g_WB + (size_t)((dir * 3 + 1) * 64 + jt) * 16384;
    const uint4* tL1b = g_WB + (size_t)((dir * 3 + 2) * 64 + jt) * 16384;
    const uint4* tFC  = g_WB + CELL_SLOTS + (size_t)(et * 8 + ks2) * 4096;

    for (int t = 0; t < TSTEPS; ++t) {
        const int p = t & 1;
        const int np = p ^ 1;
        // layer 0: z = h0_prev @ Whh0^T (+ P[feed] in epilogue)
        gemm_mma(dsm, smb, zs, g_hf[0][dir][p], g_hf[0][dir][p], 16, 16, tL0, tL0);
        cell_epilogue(dsm, zs, 0, dir, jt, np, bi0, bh0, g_hf[0][dir][np], false);
        gbar();
        // layer 1: z = h0_new @ Wih1^T + h1_prev @ Whh1^T
        gemm_mma(dsm, smb, zs, g_hf[0][dir][np], g_hf[1][dir][p], 32, 16, tL1a, tL1b);
        cell_epilogue(dsm, zs, 1, dir, jt, np, bi1, bh1, g_hf[1][dir][np], true);
        gbar();
        // fc: logits partial, K slice ks2*256..+256 (wh fragment chunks ks2*4..+4)
        gemm_mma(dsm, smb, zs, g_whf + (size_t)(ks2 * 4) * 8192,
                 g_whf, 4, 4, tFC, tFC);
        fc_epilogue(zs, et, ks2);
        gbar();
        final_phase(dsm, bid, fc_b, out, t);
        gbar();
    }
}

// ---------------- launch --------------------------------------------------------
extern "C" void kernel_launch(void* const* d_in, const int* in_sizes, int n_in,
                              void* d_out, int out_size) {
    const int* yy = (const int*)d_in[0];
    const float* h_t = (const float*)d_in[1];
    const float* h_tr = (const float*)d_in[2];
    // d_in[3] = x_lens (unused by the reference computation)
    const float* emb = (const float*)d_in[4];
    const float* W_ih = (const float*)d_in[5];
    const float* W_hh = (const float*)d_in[6];
    const float* b_ih = (const float*)d_in[7];
    const float* b_hh = (const float*)d_in[8];
    const float* W_ihr = (const float*)d_in[9];
    const float* W_hhr = (const float*)d_in[10];
    const float* b_ihr = (const float*)d_in[11];
    const float* b_hhr = (const float*)d_in[12];
    const float* c0 = (const float*)d_in[13];
    const float* c0r = (const float*)d_in[14];
    const float* fc_W = (const float*)d_in[15];
    const float* fc_b = (const float*)d_in[16];
    float* out = (float*)d_out;

    cudaFuncSetAttribute(main_kernel, cudaFuncAttributeMaxDynamicSharedMemorySize, SMEM_BYTES);
    main_kernel<<<NBLK, NTHR, SMEM_BYTES>>>(yy, h_t, h_tr, c0, c0r, emb,
                                            W_ih, W_hh, b_ih, b_hh,
                                            W_ihr, W_hhr, b_ihr, b_hhr,
                                            fc_W, fc_b, out);
}

// round 17
// speedup vs baseline: 1.1525x; 1.0164x over previous
#include <cuda_runtime.h>
#include <cuda_bf16.h>
#include <math.h>

typedef unsigned long long ull;
typedef unsigned int uint;

#define BATCH  128
#define TSTEPS 256
#define NBLK   128
#define NTHR   512

#define CELL_SLOTS 6291456u            // 384 tiles * 16384 uint4 slots
#define FC_SLOTS   524288u             // 128 tiles * 4096
#define TOT_SLOTS  (CELL_SLOTS + FC_SLOTS)

// dynamic smem map (bytes):
// four 48 KB stream buffers: [B 16KB | A-hi 16KB | A-lo 16KB] each
// zs[128][66] + hs[16][132] + final scratch live in buffer 3's space
//   (only touched after gemm-end WAIT0+sync; next gemm writes buf3 only
//    after the intervening grid barrier)
#define BUF_BYTES 49152
#define ZS_OFF    147456               // = 3*49152
#define HS_OFF    181248               // = ZS_OFF + 33792
#define SMEM_BYTES 196608

// ---------------- device scratch -------------------------------------------
__device__ float g_P[2][1024][4096];            // emb @ W_ih(l0)^T, fp32
__device__ float g_c[2][2][BATCH * 1024];
__device__ float g_logitsP[8][BATCH * 1024];    // split-K partials
__device__ int   g_feed[BATCH];
__device__ int   g_ended[BATCH];
__device__ unsigned g_cnt = 0, g_gen = 0;
__device__ uint4 g_WB[TOT_SLOTS];               // pre-fragmented split-bf16 weights
// A in mma-fragment layout: per 64-K chunk = 8192 uints (hi plane 4096 | lo plane 4096)
__device__ __align__(16) uint g_hf[2][2][2][16 * 8192];  // [layer][dir][buf]
__device__ __align__(16) uint g_whf[32 * 8192];          // scrambled fc input

// ---------------- helpers ----------------------------------------------------
__device__ __forceinline__ uint prmt(uint a, uint b, uint s) {
    uint r; asm("prmt.b32 %0, %1, %2, %3;" : "=r"(r) : "r"(a), "r"(b), "r"(s));
    return r;
}
__device__ __forceinline__ uint b2u(__nv_bfloat162 v) { return *reinterpret_cast<uint*>(&v); }
__device__ __forceinline__ uint pack_split(float v) {
    __nv_bfloat16 h = __float2bfloat16_rn(v);
    float hf = __bfloat162float(h);
    __nv_bfloat16 l = __float2bfloat16_rn(v - hf);
    return (uint)__bfloat16_as_ushort(h) | ((uint)__bfloat16_as_ushort(l) << 16);
}
__device__ __forceinline__ float sigf(float x) { return 1.0f / (1.0f + expf(-x)); }
__device__ __forceinline__ uint s2u(const void* p) {
    uint a;
    asm("{ .reg .u64 t; cvta.to.shared.u64 t, %1; cvt.u32.u64 %0, t; }" : "=r"(a) : "l"(p));
    return a;
}
// fragment slot for value pair (b-row, even j): uint index within an 8192-uint chunk
__device__ __forceinline__ int frag_slot(int brow, int j) {
    int kl = (j >> 4) & 3, pk = (j >> 1) & 7;
    return ((kl * 8 + (brow >> 4)) * 32 + (brow & 7) * 4 + (pk & 3)) * 4
           + ((brow >> 3) & 1) + 2 * (pk >> 2);
}

#define MMA_OP(d, a, bb0, bb1) \
    asm volatile( \
        "mma.sync.aligned.m16n8k16.row.col.f32.bf16.bf16.f32 " \
        "{%0,%1,%2,%3}, {%4,%5,%6,%7}, {%8,%9}, {%0,%1,%2,%3};" \
        : "+f"((d)[0]), "+f"((d)[1]), "+f"((d)[2]), "+f"((d)[3]) \
        : "r"((a)[0]), "r"((a)[1]), "r"((a)[2]), "r"((a)[3]), "r"(bb0), "r"(bb1))

#define CP_ASYNC16(daddr, saddr) \
    asm volatile("cp.async.cg.shared.global [%0], [%1], 16;" :: "r"(daddr), "l"(saddr) : "memory")
#define CP_COMMIT() asm volatile("cp.async.commit_group;" ::: "memory")
#define CP_WAIT2()  asm volatile("cp.async.wait_group 2;" ::: "memory")
#define CP_WAIT1()  asm volatile("cp.async.wait_group 1;" ::: "memory")
#define CP_WAIT0()  asm volatile("cp.async.wait_group 0;" ::: "memory")

// ---------------- f32x2 helpers (pcomp only) --------------------------------
__device__ __forceinline__ ull pk2(float lo, float hi) {
    ull r; asm("mov.b64 %0, {%1,%2};" : "=l"(r) : "f"(lo), "f"(hi)); return r;
}
__device__ __forceinline__ void fma2(ull& d, ull a, ull b) {
    asm("fma.rn.f32x2 %0, %1, %2, %0;" : "+l"(d) : "l"(a), "l"(b));
}
__device__ __forceinline__ float2 unpk(ull v) {
    float2 r; asm("mov.b64 {%0,%1}, %2;" : "=f"(r.x), "=f"(r.y) : "l"(v)); return r;
}

// ---------------- software grid barrier --------------------------------------
__device__ __forceinline__ void gbar() {
    __threadfence();
    __syncthreads();
    if (threadIdx.x == 0) {
        unsigned gen = atomicAdd(&g_gen, 0u);
        unsigned arrived = atomicAdd(&g_cnt, 1u);
        if (arrived == NBLK - 1u) {
            atomicExch(&g_cnt, 0u);
            __threadfence();
            atomicAdd(&g_gen, 1u);
        } else {
            while (atomicAdd(&g_gen, 0u) == gen) { __nanosleep(64); }
        }
        __threadfence();
    }
    __syncthreads();
}

// ---------------- init: h fragments + c + feed --------------------------------
__device__ void init_phase(int bid, const int* __restrict__ yy,
                           const float* __restrict__ h_t,
                           const float* __restrict__ h_tr,
                           const float* __restrict__ c0,
                           const float* __restrict__ c0r) {
    const int gid0 = bid * NTHR + threadIdx.x;
    const int LBH = BATCH * 1024;
    for (int i = gid0; i < 2 * 2 * 128 * 512; i += NBLK * NTHR) {
        int l = i >> 17;
        int rem = i & 131071;
        int dr = rem >> 16;
        int rem2 = rem & 65535;
        int b = rem2 >> 9;
        int pj = rem2 & 511;
        int j = pj * 2;
        const float* src = (dr ? h_tr : h_t) + (size_t)l * LBH + b * 1024 + j;
        uint ps0 = pack_split(src[0]);
        uint ps1 = pack_split(src[1]);
        uint hiU = prmt(ps0, ps1, 0x5410), loU = prmt(ps0, ps1, 0x7632);
        int cch = j >> 6;
        int slot = frag_slot(b, j);
        uint* hf = &g_hf[l][dr][0][0];
        hf[cch * 8192 + slot] = hiU;
        hf[cch * 8192 + 4096 + slot] = loU;
    }
    for (int i = gid0; i < 2 * LBH; i += NBLK * NTHR) {
        int l = i / LBH, r = i % LBH, j = r & 1023;
        g_c[l][0][r] = c0[l * 1024 + j];
        g_c[l][1][r] = c0r[l * 1024 + j];
    }
    if (bid == 0 && threadIdx.x < BATCH) {
        g_feed[threadIdx.x] = yy[threadIdx.x * TSTEPS];
        g_ended[threadIdx.x] = 0;
    }
}

// ---------------- setup: split + pre-fragment weights ------------------------
__device__ void setup_weights(int bid,
    const float* __restrict__ W_ih, const float* __restrict__ W_hh,
    const float* __restrict__ W_ihr, const float* __restrict__ W_hhr,
    const float* __restrict__ fcW) {
    for (uint s = bid * NTHR + threadIdx.x; s < TOT_SLOTS; s += NBLK * NTHR) {
        const float* p;
        if (s < CELL_SLOTS) {
            uint tile = s >> 14, rem = s & 16383u;
            uint ks = rem >> 8, nf = (rem >> 5) & 7, lane = rem & 31;
            uint dir = tile / 192, seg = (tile / 64) % 3, jt = tile & 63;
            const float* W;
            if (seg == 0)      W = dir ? W_hhr : W_hh;
            else if (seg == 1) W = (dir ? W_ihr : W_ih) + (size_t)4096 * 1024;
            else               W = (dir ? W_hhr : W_hh) + (size_t)4096 * 1024;
            uint n = nf * 8 + (lane >> 2);
            uint row = (n >> 4) * 1024 + jt * 16 + (n & 15);
            uint kb = ks * 16 + (lane & 3) * 2;
            p = W + (size_t)row * 1024 + kb;
        } else {
            uint srel = s - CELL_SLOTS;
            uint f = srel >> 12, rem = srel & 4095u;
            uint ks = rem >> 8, nf = (rem >> 5) & 7, lane = rem & 31;
            uint et = f >> 3, ks2 = f & 7;
            uint n = nf * 8 + (lane >> 2);
            uint row = et * 64 + n;
            uint kb = ks2 * 256 + ks * 16 + (lane & 3) * 2;
            p = fcW + (size_t)row * 2048 + kb;
        }
        float2 r01 = __ldg((const float2*)p);
        float2 r89 = __ldg((const float2*)(p + 8));
        __nv_bfloat162 H01 = __floats2bfloat162_rn(r01.x, r01.y);
        __nv_bfloat162 H89 = __floats2bfloat162_rn(r89.x, r89.y);
        __nv_bfloat162 L01 = __floats2bfloat162_rn(r01.x - __bfloat162float(H01.x),
                                                   r01.y - __bfloat162float(H01.y));
        __nv_bfloat162 L89 = __floats2bfloat162_rn(r89.x - __bfloat162float(H89.x),
                                                   r89.y - __bfloat162float(H89.y));
        g_WB[s] = make_uint4(b2u(H01), b2u(H89), b2u(L01), b2u(L89));
    }
}

// ---------------- pcomp (fp32 f32x2, 512 thr): P = emb @ W_ih(l0)^T ----------
__device__ void pcomp_phase(char* dsm, int bid, const float* __restrict__ emb,
                            const float* __restrict__ W_ih,
                            const float* __restrict__ W_ihr) {
    float (*As)[16][132] = (float(*)[16][132])(dsm);
    float (*Bs)[16][68]  = (float(*)[16][68])(dsm + 2 * 16 * 132 * 4);
    const int tid = threadIdx.x;
    const int ty = tid >> 4, tx = tid & 15;
    const int m0 = ty << 2, n0 = tx << 2;
    const int ar = tid >> 2, q4 = (tid & 3) << 2;
    const bool bload = (tid < 256);
    const int br = tid >> 2;

    for (int it = 0; it < 8; ++it) {
        int tile = bid + (it << 7);
        int dir = tile >> 9, mt = (tile >> 6) & 7, nt = tile & 63;
        const float* Bw = dir ? W_ihr : W_ih;
        const int m0g = mt << 7, n0g = nt << 6;
        const float* arow = emb + (size_t)(m0g + ar) * 1024 + q4;
        const float* brow = Bw + (size_t)(n0g + br) * 1024 + q4;

        ull acc[2][4];
#pragma unroll
        for (int i = 0; i < 2; i++)
#pragma unroll
            for (int j = 0; j < 4; j++) acc[i][j] = 0ULL;

        float4 pa = __ldg((const float4*)arow);
        float4 pb = make_float4(0.f, 0.f, 0.f, 0.f);
        if (bload) pb = __ldg((const float4*)brow);
        int cur = 0;
        {
            float (*A)[132] = As[0]; float (*B)[68] = Bs[0];
            A[q4+0][ar]=pa.x; A[q4+1][ar]=pa.y; A[q4+2][ar]=pa.z; A[q4+3][ar]=pa.w;
            if (bload) { B[q4+0][br]=pb.x; B[q4+1][br]=pb.y; B[q4+2][br]=pb.z; B[q4+3][br]=pb.w; }
        }
        __syncthreads();
        for (int kk = 0; kk < 64; ++kk) {
            const bool more = (kk + 1) < 64;
            if (more) {
                int k0 = (kk + 1) << 4;
                pa = __ldg((const float4*)(arow + k0));
                if (bload) pb = __ldg((const float4*)(brow + k0));
            }
            {
                const float (*A)[132] = As[cur]; const float (*B)[68] = Bs[cur];
#pragma unroll
                for (int k = 0; k < 16; k++) {
                    const ull* ap = (const ull*)&A[k][m0];
                    ull a0 = ap[0], a1 = ap[1];
                    float4 bv = *(const float4*)&B[k][n0];
                    ull p0=pk2(bv.x,bv.x), p1=pk2(bv.y,bv.y), p2=pk2(bv.z,bv.z), p3=pk2(bv.w,bv.w);
                    fma2(acc[0][0],a0,p0); fma2(acc[0][1],a0,p1); fma2(acc[0][2],a0,p2); fma2(acc[0][3],a0,p3);
                    fma2(acc[1][0],a1,p0); fma2(acc[1][1],a1,p1); fma2(acc[1][2],a1,p2); fma2(acc[1][3],a1,p3);
                }
            }
            if (more) {
                float (*A)[132] = As[cur^1]; float (*B)[68] = Bs[cur^1];
                A[q4+0][ar]=pa.x; A[q4+1][ar]=pa.y; A[q4+2][ar]=pa.z; A[q4+3][ar]=pa.w;
                if (bload) { B[q4+0][br]=pb.x; B[q4+1][br]=pb.y; B[q4+2][br]=pb.z; B[q4+3][br]=pb.w; }
                __syncthreads();
                cur ^= 1;
            }
        }
        __syncthreads();
#pragma unroll
        for (int mp = 0; mp < 2; mp++) {
            int m = m0g + m0 + (mp << 1);
#pragma unroll
            for (int j = 0; j < 4; j++) {
                float2 v = unpk(acc[mp][j]);
                g_P[dir][m][n0g + n0 + j] = v.x;
                g_P[dir][m + 1][n0g + n0 + j] = v.y;
            }
        }
        __syncthreads();
    }
}

// ---------------- HMMA GEMM core: A+B streamed, 16 warps, 16x32 tiles --------
// wm = wid&7 (16 m rows), wn = wid>>3 (32 n cols).
// Chunk buffer (48KB): B uint[0,4096) | A-hi [4096,8192) | A-lo [8192,12288).
// 4 buffers, prefetch distance 2, issue-early (buffer (c+2)&3 last read at
// chunk c-2, fenced by iteration c-1's __syncthreads -> race-free).
__device__ __forceinline__ void stream_issue(uint smb, int cn, int nch0,
    const uint* __restrict__ Af0, const uint* __restrict__ Af1,
    const uint4* __restrict__ tb0, const uint4* __restrict__ tb1, int tid) {
    int sg = (cn >= nch0);
    int cl = cn - (sg ? nch0 : 0);
    const uint4* bs = (sg ? tb1 : tb0) + (size_t)cl * 1024 + tid;
    const uint4* as = (const uint4*)((sg ? Af1 : Af0) + (size_t)cl * 8192) + tid;
    uint d = smb + (cn & 3) * BUF_BYTES + tid * 16;
#pragma unroll
    for (int i = 0; i < 2; i++) CP_ASYNC16(d + i * 8192, bs + i * 512);
    uint dA = d + 16384;
#pragma unroll
    for (int i = 0; i < 4; i++) CP_ASYNC16(dA + i * 8192, as + i * 512);
    CP_COMMIT();
}

__device__ __noinline__ void gemm_mma(char* dsm, uint smb, float (*zs)[66],
    const uint* __restrict__ Af0, const uint* __restrict__ Af1,
    int nch, int nch0,
    const uint4* __restrict__ tb0, const uint4* __restrict__ tb1) {
    const int tid = threadIdx.x;
    const int lane = tid & 31, wid = tid >> 5;
    const int wm = wid & 7, wn = wid >> 3;
    const int lq = lane >> 2, lr = lane & 3;

    float acc[4][4];
#pragma unroll
    for (int f = 0; f < 4; f++)
#pragma unroll
        for (int k = 0; k < 4; k++) acc[f][k] = 0.0f;

    stream_issue(smb, 0, nch0, Af0, Af1, tb0, tb1, tid);
    stream_issue(smb, 1, nch0, Af0, Af1, tb0, tb1, tid);

    const int aoff = wm * 128 + lane * 4;

    for (int c = 0; c < nch; ++c) {
        if (c + 2 < nch) {
            stream_issue(smb, c + 2, nch0, Af0, Af1, tb0, tb1, tid);
            CP_WAIT2();
        } else if (c + 1 < nch) {
            CP_WAIT1();
        } else {
            CP_WAIT0();
        }
        __syncthreads();

        const uint* Bu = (const uint*)(dsm + (c & 3) * BUF_BYTES);
        const uint* Au = Bu + 4096;
#pragma unroll
        for (int kl = 0; kl < 4; kl++) {
            const uint4* bp = (const uint4*)Bu + (kl * 8 + wn * 4) * 32 + lane;
            uint4 B0 = bp[0], B1 = bp[32], B2 = bp[64], B3 = bp[96];
            int base = kl * 1024 + aoff;
            uint4 aH = *(const uint4*)(Au + base);
            uint4 aL = *(const uint4*)(Au + 4096 + base);
            const uint* ah = (const uint*)&aH;
            const uint* al = (const uint*)&aL;
            // product-major (per-acc order stays hh, hl, lh -> bitwise same)
            MMA_OP(acc[0], ah, B0.x, B0.y); MMA_OP(acc[1], ah, B1.x, B1.y);
            MMA_OP(acc[2], ah, B2.x, B2.y); MMA_OP(acc[3], ah, B3.x, B3.y);
            MMA_OP(acc[0], ah, B0.z, B0.w); MMA_OP(acc[1], ah, B1.z, B1.w);
            MMA_OP(acc[2], ah, B2.z, B2.w); MMA_OP(acc[3], ah, B3.z, B3.w);
            MMA_OP(acc[0], al, B0.x, B0.y); MMA_OP(acc[1], al, B1.x, B1.y);
            MMA_OP(acc[2], al, B2.x, B2.y); MMA_OP(acc[3], al, B3.x, B3.y);
        }
    }

    // zs lives in buffer 3's space and the last chunk reads buffer 3 ->
    // fence ALL warps' reads before overwriting.
    __syncthreads();
#pragma unroll
    for (int f = 0; f < 4; f++) {
        int m = wm * 16 + lq;
        int n = wn * 32 + f * 8 + lr * 2;
        *(float2*)&zs[m][n]     = make_float2(acc[f][0], acc[f][1]);
        *(float2*)&zs[m + 8][n] = make_float2(acc[f][2], acc[f][3]);
    }
    __syncthreads();
}

// ---------------- cell epilogue: gates + state + fragment writes --------------
__device__ void cell_epilogue(char* dsm, float (*zs)[66], int layer, int dir,
    int jt, int np, const float* __restrict__ bi, const float* __restrict__ bh,
    uint* __restrict__ hfout, bool dowh) {
    const int tid = threadIdx.x;
    const int j0 = jt << 4;
    uint* hs = (uint*)(dsm + HS_OFF);   // [16][132]
    const int cch = jt >> 2, kl = jt & 3;

#pragma unroll
    for (int it = 0; it < 2; ++it) {
        int item = tid + (it << 9);       // 0..1023
        int b = item >> 3, pk = item & 7;
        int jj0 = pk * 2, jj1 = jj0 + 1;
        int jg0 = j0 + jj0, jg1 = j0 + jj1;
        float z0[4], z1[4];
        z0[0] = zs[b][jj0]      + bi[jg0]        + bh[jg0];
        z0[1] = zs[b][16 + jj0] + bi[1024 + jg0] + bh[1024 + jg0];
        z0[2] = zs[b][32 + jj0] + bi[2048 + jg0] + bh[2048 + jg0];
        z0[3] = zs[b][48 + jj0] + bi[3072 + jg0] + bh[3072 + jg0];
        z1[0] = zs[b][jj1]      + bi[jg1]        + bh[jg1];
        z1[1] = zs[b][16 + jj1] + bi[1024 + jg1] + bh[1024 + jg1];
        z1[2] = zs[b][32 + jj1] + bi[2048 + jg1] + bh[2048 + jg1];
        z1[3] = zs[b][48 + jj1] + bi[3072 + jg1] + bh[3072 + jg1];
        if (layer == 0) {
            int feed = __ldcg(&g_feed[b]);
            const float* pr = &g_P[dir][feed][0];
            z0[0] += pr[jg0]; z0[1] += pr[1024 + jg0]; z0[2] += pr[2048 + jg0]; z0[3] += pr[3072 + jg0];
            z1[0] += pr[jg1]; z1[1] += pr[1024 + jg1]; z1[2] += pr[2048 + jg1]; z1[3] += pr[3072 + jg1];
        }
        uint ps0, ps1;
        {
            float ig = sigf(z0[0]), fg = sigf(z0[1]), gv = tanhf(z0[2]), og = sigf(z0[3]);
            int idx = b * 1024 + jg0;
            float cn = fg * g_c[layer][dir][idx] + ig * gv;
            float hn = og * tanhf(cn);
            g_c[layer][dir][idx] = cn;
            ps0 = pack_split(hn);
        }
        {
            float ig = sigf(z1[0]), fg = sigf(z1[1]), gv = tanhf(z1[2]), og = sigf(z1[3]);
            int idx = b * 1024 + jg1;
            float cn = fg * g_c[layer][dir][idx] + ig * gv;
            float hn = og * tanhf(cn);
            g_c[layer][dir][idx] = cn;
            ps1 = pack_split(hn);
        }
        uint hiU = prmt(ps0, ps1, 0x5410);
        uint loU = prmt(ps0, ps1, 0x7632);
        int slot = ((kl * 8 + (b >> 4)) * 32 + (b & 7) * 4 + (pk & 3)) * 4
                   + ((b >> 3) & 1) + 2 * (pk >> 2);
        hfout[cch * 8192 + slot] = hiU;
        hfout[cch * 8192 + 4096 + slot] = loU;
        if (dowh) {
            hs[jj0 * 132 + b] = ps0;
            hs[jj1 * 132 + b] = ps1;
        }
    }
    if (dowh) {
        __syncthreads();
#pragma unroll
        for (int it = 0; it < 2; ++it) {
            int item = tid + (it << 9);
            int ccl = item >> 6, bp = item & 63;
            int b0 = bp * 2, b1 = b0 + 1;
            uint psa = hs[ccl * 132 + b0], psb = hs[ccl * 132 + b1];
            uint hiU = prmt(psa, psb, 0x5410), loU = prmt(psa, psb, 0x7632);
            int cc = (dir << 10) + (jt << 4) + ccl;
            int b2 = cc >> 4;
            int j2 = ((cc & 15) << 7) + b0;   // even
            int c2 = j2 >> 6;
            int slot = frag_slot(b2, j2);
            g_whf[c2 * 8192 + slot] = hiU;
            g_whf[c2 * 8192 + 4096 + slot] = loU;
        }
    }
}

// ---------------- fc epilogue --------------------------------------------------
__device__ __forceinline__ void fc_epilogue(float (*zs)[66], int et, int ks2) {
    const int tid = threadIdx.x;
    const int b = tid >> 2, n0 = (tid & 3) << 4;
    float* lp = &g_logitsP[ks2][b * 1024 + et * 64 + n0];
#pragma unroll
    for (int j = 0; j < 16; j++) lp[j] = zs[b][n0 + j];
}

// ---------------- final phase --------------------------------------------------
__device__ void final_phase(char* dsm, int bid, const float* __restrict__ fc_b,
                            float* __restrict__ out, int t) {
    const int b = bid;
    const int tid = threadIdx.x;
    float* sl = (float*)(dsm + ZS_OFF);
    float* sv = sl + 1024;
    int*   si = (int*)(sl + 1536);
    float* ssum = sl + 2048;

    const int end = __ldcg(&g_ended[b]);
    float bv = -3.402823466e38f;
    int bidx = 0;
    for (int e = tid; e < 1024; e += NTHR) {
        float v;
        if (end) {
            v = (e == 1) ? 1.0f : 0.0f;
        } else {
            v = fc_b[e];
#pragma unroll
            for (int s = 0; s < 8; s++) v += __ldcg(&g_logitsP[s][b * 1024 + e]);
        }
        sl[e] = v;
        if (v > bv) { bv = v; bidx = e; }
    }
    sv[tid] = bv; si[tid] = bidx;
    __syncthreads();
    for (int s = NTHR / 2; s > 0; s >>= 1) {
        if (tid < s) {
            float v2 = sv[tid + s]; int i2 = si[tid + s];
            if (v2 > sv[tid] || (v2 == sv[tid] && i2 < si[tid])) { sv[tid] = v2; si[tid] = i2; }
        }
        __syncthreads();
    }
    float mx = sv[0];
    int label = si[0];
    __syncthreads();

    float ps = 0.0f;
    for (int e = tid; e < 1024; e += NTHR) ps += expf(sl[e] - mx);
    ssum[tid] = ps;
    __syncthreads();
    for (int s = NTHR / 2; s > 0; s >>= 1) {
        if (tid < s) ssum[tid] += ssum[tid + s];
        __syncthreads();
    }
    float inv = 1.0f / ssum[0];

    float* orow = out + ((size_t)b * TSTEPS + t) * 1024;
    for (int e = tid; e < 1024; e += NTHR) orow[e] = expf(sl[e] - mx) * inv;

    if (tid == 0) {
        g_feed[b] = label;
        g_ended[b] = end | (label == 1);  // EOS = 1
    }
}

// ---------------- mega kernel --------------------------------------------------
__global__ void __launch_bounds__(NTHR, 1) main_kernel(
    const int* __restrict__ yy,
    const float* __restrict__ h_t, const float* __restrict__ h_tr,
    const float* __restrict__ c0, const float* __restrict__ c0r,
    const float* __restrict__ emb,
    const float* __restrict__ W_ih, const float* __restrict__ W_hh,
    const float* __restrict__ b_ih, const float* __restrict__ b_hh,
    const float* __restrict__ W_ihr, const float* __restrict__ W_hhr,
    const float* __restrict__ b_ihr, const float* __restrict__ b_hhr,
    const float* __restrict__ fcW, const float* __restrict__ fc_b,
    float* __restrict__ out) {
    extern __shared__ char dsm[];
    const uint smb = s2u(dsm);
    float (*zs)[66] = (float(*)[66])(dsm + ZS_OFF);
    const int bid = blockIdx.x;

    init_phase(bid, yy, h_t, h_tr, c0, c0r);
    setup_weights(bid, W_ih, W_hh, W_ihr, W_hhr, fcW);
    pcomp_phase(dsm, bid, emb, W_ih, W_ihr);
    gbar();

    const int dir = bid >> 6;
    const int jt = bid & 63;
    const int et = bid >> 3;
    const int ks2 = bid & 7;
    const float* bi0 = (dir ? b_ihr : b_ih);
    const float* bh0 = (dir ? b_hhr : b_hh);
    const float* bi1 = bi0 + 4096;
    const float* bh1 = bh0 + 4096;
    const uint4* tL0  = g_WB + (size_t)((dir * 3 + 0) * 64 + jt) * 16384;
    const uint4* tL1a = g_WB + (size_t)((dir * 3 + 1) * 64 + jt) * 16384;
    const uint4* tL1b = g_WB + (size_t)((dir * 3 + 2) * 64 + jt) * 16384;
    const uint4* tFC  = g_WB + CELL_SLOTS + (size_t)(et * 8 + ks2) * 4096;

    for (int t = 0; t < TSTEPS; ++t) {
        const int p = t & 1;
        const int np = p ^ 1;
        // layer 0: z = h0_prev @ Whh0^T (+ P[feed] in epilogue)
        gemm_mma(dsm, smb, zs, g_hf[0][dir][p], g_hf[0][dir][p], 16, 16, tL0, tL0);
        cell_epilogue(dsm, zs, 0, dir, jt, np, bi0, bh0, g_hf[0][dir][np], false);
        gbar();
        // layer 1: z = h0_new @ Wih1^T + h1_prev @ Whh1^T
        gemm_mma(dsm, smb, zs, g_hf[0][dir][np], g_hf[1][dir][p], 32, 16, tL1a, tL1b);
        cell_epilogue(dsm, zs, 1, dir, jt, np, bi1, bh1, g_hf[1][dir][np], true);
        gbar();
        // fc: logits partial, K slice ks2*256..+256 (wh fragment chunks ks2*4..+4)
        gemm_mma(dsm, smb, zs, g_whf + (size_t)(ks2 * 4) * 8192,
                 g_whf, 4, 4, tFC, tFC);
        fc_epilogue(zs, et, ks2);
        gbar();
        final_phase(dsm, bid, fc_b, out, t);
        gbar();
    }
}

// ---------------- launch --------------------------------------------------------
extern "C" void kernel_launch(void* const* d_in, const int* in_sizes, int n_in,
                              void* d_out, int out_size) {
    const int* yy = (const int*)d_in[0];
    const float* h_t = (const float*)d_in[1];
    const float* h_tr = (const float*)d_in[2];
    // d_in[3] = x_lens (unused by the reference computation)
    const float* emb = (const float*)d_in[4];
    const float* W_ih = (const float*)d_in[5];
    const float* W_hh = (const float*)d_in[6];
    const float* b_ih = (const float*)d_in[7];
    const float* b_hh = (const float*)d_in[8];
    const float* W_ihr = (const float*)d_in[9];
    const float* W_hhr = (const float*)d_in[10];
    const float* b_ihr = (const float*)d_in[11];
    const float* b_hhr = (const float*)d_in[12];
    const float* c0 = (const float*)d_in[13];
    const float* c0r = (const float*)d_in[14];
    const float* fc_W = (const float*)d_in[15];
    const float* fc_b = (const float*)d_in[16];
    float* out = (float*)d_out;

    cudaFuncSetAttribute(main_kernel, cudaFuncAttributeMaxDynamicSharedMemorySize, SMEM_BYTES);
    main_kernel<<<NBLK, NTHR, SMEM_BYTES>>>(yy, h_t, h_tr, c0, c0r, emb,
                                            W_ih, W_hh, b_ih, b_hh,
                                            W_ihr, W_hhr, b_ihr, b_hhr,
                                            fc_W, fc_b, out);
}